// round 3
// baseline (speedup 1.0000x reference)
#include <cuda_runtime.h>

#define VS 100
#define BATCH 8
#define NUM_COORDS 65536
#define NPTS (BATCH * NUM_COORDS)          // 524288
#define NCELLS (BATCH * VS * VS * VS)      // 8,000,000

// Scratch: zero-initialized at module load; finalize re-zeroes exactly the
// occupied cells it consumes, so graph replays are deterministic with no
// explicit clear pass.
__device__ float g_sum[(size_t)NCELLS * 8];  // 256 MB; ch0..5 = sums
__device__ float g_cnt[NCELLS];              // 32 MB compact counts

__global__ void __launch_bounds__(256) scatter_kernel(
    const float* __restrict__ coords,
    const float* __restrict__ feats)
{
    int idx = blockIdx.x * blockDim.x + threadIdx.x;
    if (idx >= NPTS) return;

    float x = coords[idx * 3 + 0];
    float y = coords[idx * 3 + 1];
    float z = coords[idx * 3 + 2];

    // Reference constants collapse in f32: res = denom = 0.01f, shift = -0.01f
    int ix = (int)floorf((x + 0.01f) / 0.01f);
    int iy = (int)floorf((y + 0.01f) / 0.01f);
    int iz = (int)floorf((z + 0.01f) / 0.01f);

    // Indices outside [1,VS] land in the halo the reference slices away.
    if (ix < 1 || ix > VS || iy < 1 || iy > VS || iz < 1 || iz > VS) return;

    int b = idx >> 16;  // NUM_COORDS = 65536
    int cell = ((b * VS + (ix - 1)) * VS + (iy - 1)) * VS + (iz - 1);

    float f0 = feats[idx * 3 + 0];
    float f1 = feats[idx * 3 + 1];
    float f2 = feats[idx * 3 + 2];

    float* s = &g_sum[(size_t)cell * 8];
    // Vectorized return-less reductions (sm_90+): 3 atomic ops instead of 7.
    asm volatile("red.global.add.v4.f32 [%0], {%1, %2, %3, %4};"
                 :: "l"(s), "f"(x), "f"(y), "f"(z), "f"(f0) : "memory");
    asm volatile("red.global.add.v2.f32 [%0], {%1, %2};"
                 :: "l"(s + 4), "f"(f1), "f"(f2) : "memory");
    atomicAdd(&g_cnt[cell], 1.0f);
}

// 2 cells per thread: 512 cells/block, 15625 blocks (exact).
__global__ void __launch_bounds__(256) finalize_kernel(float* __restrict__ out)
{
    __shared__ float stage[512 * 10];  // 20 KB

    int base = blockIdx.x * 512;

    // Issue both count loads up front (MLP=2, independent scoreboards).
    float cnt0 = g_cnt[base + threadIdx.x];
    float cnt1 = g_cnt[base + threadIdx.x + 256];

#pragma unroll
    for (int q = 0; q < 2; q++) {
        int cl = threadIdx.x + q * 256;
        int cell = base + cl;
        float cnt = q ? cnt1 : cnt0;

        // Decode (i, j, k) within the batch's 100^3 block.
        int k = cell % VS;
        int t = cell / VS;
        int j = t % VS;
        int i = (t / VS) % VS;

        float v0 = 0.f, v1 = 0.f, v2 = 0.f, v3 = 0.f, v4 = 0.f, v5 = 0.f;
        float occ = 0.f;
        if (cnt > 0.0f) {
            float4* sp = (float4*)&g_sum[(size_t)cell * 8];
            float4 a  = __ldcs((const float4*)sp);
            float4 b4 = __ldcs((const float4*)sp + 1);
            float r = 1.0f / cnt;  // one divide, six muls (<=1 ulp vs per-elem div)
            v0 = a.x * r;
            v1 = a.y * r;
            v2 = a.z * r;
            v3 = a.w * r;
            v4 = b4.x * r;
            v5 = b4.y * r;
            occ = 1.0f;
            // Self-clean scratch for the next graph replay.
            float4 z4 = make_float4(0.f, 0.f, 0.f, 0.f);
            __stcs(sp, z4);
            __stcs(sp + 1, z4);
            g_cnt[cell] = 0.0f;
        }

        int sb = cl * 10;
        stage[sb + 0] = v0;
        stage[sb + 1] = v1;
        stage[sb + 2] = v2;
        stage[sb + 3] = v3;
        stage[sb + 4] = v4;
        stage[sb + 5] = v5;
        stage[sb + 6] = (float)i * 0.01f;
        stage[sb + 7] = (float)j * 0.01f;
        stage[sb + 8] = (float)k * 0.01f;
        stage[sb + 9] = occ;
    }
    __syncthreads();

    // 512 cells * 10 f32 = 1280 float4, fully coalesced streaming stores.
    float4* o4 = (float4*)(out + (size_t)blockIdx.x * 5120);
    const float4* s4 = (const float4*)stage;
#pragma unroll
    for (int w = threadIdx.x; w < 1280; w += 256) {
        __stcs(o4 + w, s4[w]);
    }
}

extern "C" void kernel_launch(void* const* d_in, const int* in_sizes, int n_in,
                              void* d_out, int out_size)
{
    const float* coords = (const float*)d_in[0];
    const float* feats  = (const float*)d_in[1];
    float* out = (float*)d_out;

    scatter_kernel<<<(NPTS + 255) / 256, 256>>>(coords, feats);
    finalize_kernel<<<NCELLS / 512, 256>>>(out);  // 15625 blocks
}